// round 10
// baseline (speedup 1.0000x reference)
#include <cuda_runtime.h>
#include <cstdint>

// ============================================================================
// BiSDA_3977139716506 — exact algebraic simplification (proof in R2).
//
// The final LIF (tau=2, V_TH=1, v_reset=0) receives inputs in [0,1]; its
// membrane obeys v_t <= 1 - 2^-t < 1, so it can never fire: its output is
// exactly zero for every input. Then pw @ 0 = 0 and BatchNorm(0) = beta:
//
//     reference(...) == broadcast(p_beta[c]) over [T=4, B=2, C=128, 8,32,32]
//
// Verified rel_err = 0.0 across R1 (full compute) and all broadcast variants.
//
// R8 lesson: driver memset fills at ~6 TB/s while my STG.128 kernels pin at
// ~4.2 TB/s -> the limiter is the per-warp store-instruction / L1tex
// wavefront rate, not the L2 fabric. But a second graph node (even an
// early-exit guard) costs ~4 us, so memset+guard loses to one fused kernel.
//
// This round: single-node broadcast using sm_100+ 256-bit stores
// (st.global.v8.f32): one warp instruction writes 1024 contiguous bytes,
// halving store-instruction and wavefront count vs STG.128.
//
// Layout: v8-store index i8 covers floats [i8*8, i8*8+8); channel
// c = (i8 >> 10) & 127. Partition stride 262144 is a multiple of 1024, so
// the per-partition beta load is warp-uniform. d_out is cudaMalloc'd
// (256 B aligned); every v8 address is 32 B aligned.
// ============================================================================

#define NTHREADS 262144           // 512 blocks * 512 threads
                                  // total v8 stores = 8388608/8 = 1048576 = 4*NTHREADS

__global__ void __launch_bounds__(512) broadcast_beta_v8_kernel(
    const float* __restrict__ p_beta, float* __restrict__ out)
{
    int i = blockIdx.x * 512 + threadIdx.x;      // [0, NTHREADS)
#pragma unroll
    for (int j = 0; j < 4; j++) {
        int i8 = i + j * NTHREADS;               // lane-contiguous v8 index
        float b = __ldg(&p_beta[(i8 >> 10) & 127]);
        float* p = out + (size_t)i8 * 8;
        asm volatile(
            "st.global.v8.f32 [%0], {%1,%1,%1,%1,%1,%1,%1,%1};"
            :: "l"(p), "f"(b) : "memory");
    }
}

extern "C" void kernel_launch(void* const* d_in, const int* in_sizes, int n_in,
                              void* d_out, int out_size)
{
    // metadata order: x, qw, q_gamma, q_beta, kw, k_gamma, k_beta,
    //                 v_gamma, v_beta, pw, p_gamma, p_beta
    const float* p_beta = (const float*)d_in[11];

    broadcast_beta_v8_kernel<<<512, 512>>>(p_beta, (float*)d_out);
}